// round 16
// baseline (speedup 1.0000x reference)
#include <cuda_runtime.h>
#include <cuda_bf16.h>
#include <cstddef>

#define TT    1024
#define BB    256
#define INDIM 128
#define HH    256
#define NG    16     // batch groups of 16 rows; 6 CTAs each

typedef unsigned long long ull;
typedef unsigned int uint;

// ---------------- scratch (device globals) ----------------
__device__ float g_X0[(size_t)TT * BB * HH];      // input proj + biases (fp32)
__device__ float g_h1all[(size_t)TT * BB * HH];   // all layer-1 hidden (fp32, for logits)
__device__ float g_h0last[BB * HH];
__device__ float g_h1last[BB * HH];
// s8 A-fragment rings (IMMA m16n8k32 layout), group-local:
// uint idx = ver*1024 + ksb*128 + lane*4 + reg ; byte of uint = k&3
__device__ uint g_h0F[4][NG][2048];
__device__ uint g_h1F[4][NG][2048];
__device__ __align__(128) unsigned g_cnt0[NG * 32];
__device__ __align__(128) unsigned g_cnt1[NG * 32];

// ---------------- acq/rel primitives ----------------
__device__ __forceinline__ unsigned arrive_acqrel(unsigned* p) {
    unsigned r;
    asm volatile("atom.acq_rel.gpu.global.add.u32 %0, [%1], 1;" : "=r"(r) : "l"(p) : "memory");
    return r;
}
__device__ __forceinline__ unsigned ld_acq_u(const unsigned* p) {
    unsigned r;
    asm volatile("ld.acquire.gpu.global.u32 %0, [%1];" : "=r"(r) : "l"(p) : "memory");
    return r;
}

__device__ __forceinline__ float tanh_fast(float x) {
    float xc = fminf(fmaxf(x, -15.0f), 15.0f);
    float e  = __expf(2.0f * xc);
    return __fdividef(e - 1.0f, e + 1.0f);
}
// bf16 split (prologue only)
__device__ __forceinline__ void split2(float a, float b, uint& hi, uint& lo) {
    __nv_bfloat162 h = __floats2bfloat162_rn(a, b);
    float ha = __bfloat162float(h.x), hb = __bfloat162float(h.y);
    __nv_bfloat162 l = __floats2bfloat162_rn(a - ha, b - hb);
    hi = *(uint*)&h; lo = *(uint*)&l;
}
// s16 fixed-point limb split
__device__ __forceinline__ void qlimbs(float v, float scale, int& hi, int& lo) {
    int q = __float2int_rn(v * scale);
    hi = (q + 128) >> 8;
    lo = q - (hi << 8);
}
__device__ __forceinline__ uint pack4(int a, int b, int c, int d) {
    return (uint)(unsigned char)a | ((uint)(unsigned char)b << 8) |
           ((uint)(unsigned char)c << 16) | ((uint)(unsigned char)d << 24);
}
__device__ __forceinline__ unsigned short pack2s(int a, int b) {
    return (unsigned short)((uint)(unsigned char)a | ((uint)(unsigned char)b << 8));
}

#define MMA16816(d, a, b) \
    asm volatile("mma.sync.aligned.m16n8k16.row.col.f32.bf16.bf16.f32 " \
        "{%0,%1,%2,%3}, {%4,%5,%6,%7}, {%8,%9}, {%0,%1,%2,%3};" \
        : "+f"(d[0]), "+f"(d[1]), "+f"(d[2]), "+f"(d[3]) \
        : "r"((a).x), "r"((a).y), "r"((a).z), "r"((a).w), "r"((b).x), "r"((b).y))

#define IMMA16832(d, a, b) \
    asm volatile("mma.sync.aligned.m16n8k32.row.col.s32.s8.s8.s32 " \
        "{%0,%1,%2,%3}, {%4,%5,%6,%7}, {%8,%9}, {%0,%1,%2,%3};" \
        : "+r"((d)[0]), "+r"((d)[1]), "+r"((d)[2]), "+r"((d)[3]) \
        : "r"((a).x), "r"((a).y), "r"((a).z), "r"((a).w), "r"((b).x), "r"((b).y))

#define S16C 3.0517578125e-05f        // 2^-15
#define S8C  1.1920928955078125e-07f  // 2^-23

// =====================================================================
// Seed: pack initial hidden into s8 limb frag rings (slot 3); reset counters.
// =====================================================================
__global__ void __launch_bounds__(256) k_seed(const float* __restrict__ hidden) {
    int bx = blockIdx.x, tid = threadIdx.x;
    if (bx == 8) {
        if (tid < NG) { g_cnt0[tid * 32] = 0; g_cnt1[tid * 32] = 0; }
        return;
    }
    for (int s = 0; s < 16; ++s) {
        int it = bx * 4096 + s * 256 + tid;        // 0..32767
        int tensor = it >> 14;
        int rem = it & 16383;
        int b = rem >> 6, k4 = (rem & 63) << 2;
        float4 hv = *(const float4*)&hidden[(size_t)tensor * BB * HH + b * HH + k4];
        int h0,l0,h1,l1,h2,l2,h3,l3;
        qlimbs(hv.x, 16384.f, h0, l0); qlimbs(hv.y, 16384.f, h1, l1);
        qlimbs(hv.z, 16384.f, h2, l2); qlimbs(hv.w, 16384.f, h3, l3);
        uint uH = pack4(h0,h1,h2,h3), uL = pack4(l0,l1,l2,l3);
        int r = b & 15, grp = b >> 4;
        int lane = ((r & 7) << 2) | ((k4 >> 2) & 3);
        int reg = ((r >> 3) & 1) | (((k4 >> 4) & 1) << 1);
        int idx = (k4 >> 5) * 128 + lane * 4 + reg;
        uint* ring = (tensor == 0) ? g_h0F[3][grp] : g_h1F[3][grp];
        ring[idx] = uH; ring[1024 + idx] = uL;
    }
}

// =====================================================================
// Prologue (tensor-core bf16 3-term, validated R13): X0 = inp @ Wih0^T + biases.
// =====================================================================
#define PRO2_SMEM 157184
__global__ void __launch_bounds__(256, 1) k_pro2(
    const float* __restrict__ inp, const float* __restrict__ Wih0,
    const float* __restrict__ bih0, const float* __restrict__ bhh0,
    const float* __restrict__ bias0)
{
    extern __shared__ char smch[];
    uint*  sw   = (uint*)smch;
    float* sa   = (float*)(smch + 131072);
    float* sout = (float*)(smch + 139520);
    float* sb   = (float*)(smch + 156160);

    const int bx = blockIdx.x, tid = threadIdx.x;
    const int lane = tid & 31, wi = tid >> 5;
    const int gID = lane >> 2, tig = lane & 3;
    const int acol = tig * 2;

    for (int i = tid; i < 8192; i += 256) {
        int j = i >> 5, k4 = (i & 31) << 2;
        float4 w = *(const float4*)&Wih0[(size_t)j * INDIM + k4];
        uint h01, l01, h23, l23;
        split2(w.x, w.y, h01, l01);
        split2(w.z, w.w, h23, l23);
        int lane0 = ((j & 7) << 2) | ((k4 >> 1) & 3);
        int reg = (k4 >> 3) & 1, ksb = k4 >> 4, ng = j >> 3;
        int b0 = ((0 * 8 + ksb) * 32 + ng) * 32;
        int b1 = ((1 * 8 + ksb) * 32 + ng) * 32;
        sw[(b0 + lane0) * 2 + reg]     = h01;
        sw[(b0 + lane0 + 1) * 2 + reg] = h23;
        sw[(b1 + lane0) * 2 + reg]     = l01;
        sw[(b1 + lane0 + 1) * 2 + reg] = l23;
    }
    if (tid < 256) sb[tid] = bih0[tid] + bhh0[tid] + bias0[tid];
    __syncthreads();

    for (int mt = bx; mt < 16384; mt += 148) {
        const size_t r0 = (size_t)mt * 16;
        #pragma unroll
        for (int it = 0; it < 2; ++it) {
            int i = tid + it * 256;
            int row = i >> 5, c4 = (i & 31) << 2;
            *(float4*)&sa[row * 132 + c4] = *(const float4*)&inp[(r0 + row) * INDIM + c4];
        }
        __syncthreads();

        uint4 aH[8], aL[8];
        #pragma unroll
        for (int ksb = 0; ksb < 8; ++ksb) {
            int cb = ksb * 16 + acol;
            float2 p0 = *(const float2*)&sa[gID * 132 + cb];
            float2 p1 = *(const float2*)&sa[(gID + 8) * 132 + cb];
            float2 p2 = *(const float2*)&sa[gID * 132 + cb + 8];
            float2 p3 = *(const float2*)&sa[(gID + 8) * 132 + cb + 8];
            split2(p0.x, p0.y, aH[ksb].x, aL[ksb].x);
            split2(p1.x, p1.y, aH[ksb].y, aL[ksb].y);
            split2(p2.x, p2.y, aH[ksb].z, aL[ksb].z);
            split2(p3.x, p3.y, aH[ksb].w, aL[ksb].w);
        }

        float acc[4][4];
        #pragma unroll
        for (int n2 = 0; n2 < 4; ++n2)
            #pragma unroll
            for (int q = 0; q < 4; ++q) acc[n2][q] = 0.0f;

        #pragma unroll
        for (int ksb = 0; ksb < 8; ++ksb) {
            #pragma unroll
            for (int n2 = 0; n2 < 4; ++n2) {
                int ngg = wi * 4 + n2;
                uint2 bH = *(const uint2*)&sw[(((0 * 8 + ksb) * 32 + ngg) * 32 + lane) * 2];
                uint2 bL = *(const uint2*)&sw[(((1 * 8 + ksb) * 32 + ngg) * 32 + lane) * 2];
                MMA16816(acc[n2], aH[ksb], bH);
                MMA16816(acc[n2], aL[ksb], bH);
                MMA16816(acc[n2], aH[ksb], bL);
            }
        }
        __syncthreads();

        #pragma unroll
        for (int n2 = 0; n2 < 4; ++n2) {
            int j = (wi * 4 + n2) * 8 + acol;
            float2 bb = *(const float2*)&sb[j];
            *(float2*)&sout[gID * 260 + j]       = make_float2(acc[n2][0] + bb.x, acc[n2][1] + bb.y);
            *(float2*)&sout[(gID + 8) * 260 + j] = make_float2(acc[n2][2] + bb.x, acc[n2][3] + bb.y);
        }
        __syncthreads();

        #pragma unroll
        for (int it = 0; it < 4; ++it) {
            int li = tid + it * 256;
            int row = li >> 6, c4 = (li & 63) << 2;
            *(float4*)&g_X0[(r0 + row) * HH + c4] = *(const float4*)&sout[row * 260 + c4];
        }
        __syncthreads();
    }
}

// =====================================================================
// Persistent recurrence, INT8 IMMA v3: latency-overlapped.
// Layer0: own-half fragments self-supplied via CTA-local smem; peer-half
// wait polled AFTER own-half IMMAs. Layer1: two-phase (h1 part early,
// h0 part after layer0's arrive).
// =====================================================================
#define RNN_SMEM 69632
__global__ void __launch_bounds__(256, 1) k_rnn(
    const float* __restrict__ Whh0, const float* __restrict__ Wih1,
    const float* __restrict__ Whh1, const float* __restrict__ bih1,
    const float* __restrict__ bhh1, const float* __restrict__ bias1)
{
    extern __shared__ uint smu[];
    const int bx = blockIdx.x, tid = threadIdx.x;
    const int lane = tid & 31, wi = tid >> 5;
    const int gID = lane >> 2, tig = lane & 3;
    const int g = bx / 6, role = bx % 6, g32 = g * 32;
    const int b0 = g * 16;
    uint* sw = smu;   // W frags: 16384 uints (64KB) both layers

    if (role < 2) {
        // ================= layer 0: m16 x n128 x k256 =================
        const int jg0 = role * 128;
        const int ksb0 = role * 4;          // own ksb range (self-produced cols)
        const int pksb0 = (role ^ 1) * 4;   // peer ksb range
        uint* sfrag = smu + 16384;          // own-half frags: [2 ver][4 ksb][128] = 1024 uints

        for (int i = tid; i < 8192; i += 256) {
            int jl = i >> 6, k4 = (i & 63) << 2;
            float4 w = *(const float4*)&Whh0[(size_t)(jg0 + jl) * HH + k4];
            int h0,l0,h1,l1,h2,l2,h3,l3;
            qlimbs(w.x, 131072.f, h0, l0); qlimbs(w.y, 131072.f, h1, l1);
            qlimbs(w.z, 131072.f, h2, l2); qlimbs(w.w, 131072.f, h3, l3);
            int lane0 = ((jl & 7) << 2) | ((k4 >> 2) & 3);
            int reg = (k4 >> 4) & 1, ksb = k4 >> 5, ng = jl >> 3;
            sw[(((0 * 8 + ksb) * 16 + ng) * 64) + lane0 * 2 + reg] = pack4(h0,h1,h2,h3);
            sw[(((1 * 8 + ksb) * 16 + ng) * 64) + lane0 * 2 + reg] = pack4(l0,l1,l2,l3);
        }

        const int jb = jg0 + wi * 16;

        for (int t = 0; t < TT; ++t) {
            // ring-overwrite guard only (rarely binding)
            if (tid == 32) { while ((int)ld_acq_u(&g_cnt1[g32]) < 4 * (t - 3)) { } }
            __syncthreads();

            // own-half A frags: self-produced (smem), or seed ring at t=0
            uint4 aHo[4], aLo[4];
            if (t == 0) {
                const uint* seed = g_h0F[3][g];
                #pragma unroll
                for (int k = 0; k < 4; ++k) {
                    aHo[k] = __ldcg((const uint4*)&seed[(ksb0 + k) * 128 + lane * 4]);
                    aLo[k] = __ldcg((const uint4*)&seed[1024 + (ksb0 + k) * 128 + lane * 4]);
                }
            } else {
                #pragma unroll
                for (int k = 0; k < 4; ++k) {
                    aHo[k] = *(const uint4*)&sfrag[k * 128 + lane * 4];
                    aLo[k] = *(const uint4*)&sfrag[512 + k * 128 + lane * 4];
                }
            }
            __syncthreads();   // sfrag reads done before epilogue overwrite

            // X0 prefetch
            float2 px[2][2];
            #pragma unroll
            for (int n2 = 0; n2 < 2; ++n2) {
                int j = jb + n2 * 8 + 2 * tig;
                px[n2][0] = __ldcs((const float2*)&g_X0[((size_t)t * BB + b0 + gID) * HH + j]);
                px[n2][1] = __ldcs((const float2*)&g_X0[((size_t)t * BB + b0 + gID + 8) * HH + j]);
            }

            int accA[2][4], accB[2][4], accC[2][4];
            #pragma unroll
            for (int n2 = 0; n2 < 2; ++n2)
                #pragma unroll
                for (int q = 0; q < 4; ++q) { accA[n2][q] = 0; accB[n2][q] = 0; accC[n2][q] = 0; }

            // own-half IMMAs (overlaps peer's epilogue/arrive in wall time)
            #pragma unroll
            for (int k = 0; k < 4; ++k) {
                #pragma unroll
                for (int n2 = 0; n2 < 2; ++n2) {
                    int ngg = wi * 2 + n2;
                    uint2 bH = *(uint2*)&sw[((0 * 8 + ksb0 + k) * 16 + ngg) * 64 + lane * 2];
                    uint2 bL = *(uint2*)&sw[((1 * 8 + ksb0 + k) * 16 + ngg) * 64 + lane * 2];
                    IMMA16832(accA[n2], aHo[k], bH);
                    IMMA16832(accB[n2], aHo[k], bL);
                    IMMA16832(accC[n2], aLo[k], bH);
                }
            }

            // now wait for peer half of h0(t-1) (usually already arrived)
            if (tid == 0) { while ((int)ld_acq_u(&g_cnt0[g32]) < 2 * t) { } }
            __syncthreads();

            const uint* srcA = g_h0F[(t + 3) & 3][g];
            uint4 aHp[4], aLp[4];
            #pragma unroll
            for (int k = 0; k < 4; ++k) {
                aHp[k] = __ldcg((const uint4*)&srcA[(pksb0 + k) * 128 + lane * 4]);
                aLp[k] = __ldcg((const uint4*)&srcA[1024 + (pksb0 + k) * 128 + lane * 4]);
            }
            #pragma unroll
            for (int k = 0; k < 4; ++k) {
                #pragma unroll
                for (int n2 = 0; n2 < 2; ++n2) {
                    int ngg = wi * 2 + n2;
                    uint2 bH = *(uint2*)&sw[((0 * 8 + pksb0 + k) * 16 + ngg) * 64 + lane * 2];
                    uint2 bL = *(uint2*)&sw[((1 * 8 + pksb0 + k) * 16 + ngg) * 64 + lane * 2];
                    IMMA16832(accA[n2], aHp[k], bH);
                    IMMA16832(accB[n2], aHp[k], bL);
                    IMMA16832(accC[n2], aLp[k], bH);
                }
            }

            // epilogue: values, quantize, sfrag (own) + ring (own half) stores
            float v[2][4];
            uint* ring = g_h0F[t & 3][g];
            int cc0 = jb + 2 * tig;
            #pragma unroll
            for (int n2 = 0; n2 < 2; ++n2) {
                int cc = cc0 + n2 * 8;
                float d0 = (float)accA[n2][0] * S16C + (float)(accB[n2][0] + accC[n2][0]) * S8C;
                float d1 = (float)accA[n2][1] * S16C + (float)(accB[n2][1] + accC[n2][1]) * S8C;
                float d2 = (float)accA[n2][2] * S16C + (float)(accB[n2][2] + accC[n2][2]) * S8C;
                float d3 = (float)accA[n2][3] * S16C + (float)(accB[n2][3] + accC[n2][3]) * S8C;
                v[n2][0] = tanh_fast(d0 + px[n2][0].x);
                v[n2][1] = tanh_fast(d1 + px[n2][0].y);
                v[n2][2] = tanh_fast(d2 + px[n2][1].x);
                v[n2][3] = tanh_fast(d3 + px[n2][1].y);
                int h00,l00,h01_,l01_,h10,l10,h11,l11;
                qlimbs(v[n2][0], 16384.f, h00, l00); qlimbs(v[n2][1], 16384.f, h01_, l01_);
                qlimbs(v[n2][2], 16384.f, h10, l10); qlimbs(v[n2][3], 16384.f, h11, l11);
                int ksb_c = cc >> 5;
                int lane_c = (gID << 2) | ((cc & 15) >> 2);
                int sub = (((cc >> 4) & 1) << 1);
                int boff = cc & 2;
                int idx0 = ksb_c * 128 + lane_c * 4 + sub;
                *(unsigned short*)((char*)(ring + idx0) + boff)            = pack2s(h00, h01_);
                *(unsigned short*)((char*)(ring + idx0 + 1) + boff)        = pack2s(h10, h11);
                *(unsigned short*)((char*)(ring + 1024 + idx0) + boff)     = pack2s(l00, l01_);
                *(unsigned short*)((char*)(ring + 1024 + idx0 + 1) + boff) = pack2s(l10, l11);
                int lidx0 = (ksb_c - ksb0) * 128 + lane_c * 4 + sub;
                *(unsigned short*)((char*)(sfrag + lidx0) + boff)           = pack2s(h00, h01_);
                *(unsigned short*)((char*)(sfrag + lidx0 + 1) + boff)       = pack2s(h10, h11);
                *(unsigned short*)((char*)(sfrag + 512 + lidx0) + boff)     = pack2s(l00, l01_);
                *(unsigned short*)((char*)(sfrag + 512 + lidx0 + 1) + boff) = pack2s(l10, l11);
            }

            __syncthreads();
            if (tid == 0) arrive_acqrel(&g_cnt0[g32]);

            if (t == TT - 1) {
                #pragma unroll
                for (int n2 = 0; n2 < 2; ++n2) {
                    int cc = cc0 + n2 * 8;
                    *(float2*)&g_h0last[(b0 + gID) * HH + cc]     = make_float2(v[n2][0], v[n2][1]);
                    *(float2*)&g_h0last[(b0 + gID + 8) * HH + cc] = make_float2(v[n2][2], v[n2][3]);
                }
            }
        }
    } else {
        // ================= layer 1: m16 x n64 x k512, two-phase =================
        const int q64 = role - 2;
        const int jq0 = q64 * 64;

        for (int i = tid; i < 8192; i += 256) {
            int jl = i >> 7, k4 = (i & 127) << 2;
            float4 w = (k4 < 256)
                ? *(const float4*)&Wih1[(size_t)(jq0 + jl) * HH + k4]
                : *(const float4*)&Whh1[(size_t)(jq0 + jl) * HH + (k4 - 256)];
            int h0,l0,h1,l1,h2,l2,h3,l3;
            qlimbs(w.x, 131072.f, h0, l0); qlimbs(w.y, 131072.f, h1, l1);
            qlimbs(w.z, 131072.f, h2, l2); qlimbs(w.w, 131072.f, h3, l3);
            int lane0 = ((jl & 7) << 2) | ((k4 >> 2) & 3);
            int reg = (k4 >> 4) & 1, ksb = k4 >> 5, ng = jl >> 3;
            sw[(((0 * 16 + ksb) * 8 + ng) * 64) + lane0 * 2 + reg] = pack4(h0,h1,h2,h3);
            sw[(((1 * 16 + ksb) * 8 + ng) * 64) + lane0 * 2 + reg] = pack4(l0,l1,l2,l3);
        }

        const int jb = jq0 + wi * 8 + 2 * tig;
        const float bbx = bih1[jb] + bhh1[jb] + bias1[jb];
        const float bby = bih1[jb + 1] + bhh1[jb + 1] + bias1[jb + 1];

        for (int t = 0; t < TT; ++t) {
            int accA[2][4], accB[2][4], accC[2][4];
            #pragma unroll
            for (int p = 0; p < 2; ++p)
                #pragma unroll
                for (int q = 0; q < 4; ++q) { accA[p][q] = 0; accB[p][q] = 0; accC[p][q] = 0; }

            // phase 1: peers' h1(t-1) — available since previous step's end
            if (tid == 0) { while ((int)ld_acq_u(&g_cnt1[g32]) < 4 * t) { } }
            __syncthreads();
            {
                const uint* s1 = g_h1F[(t + 3) & 3][g];
                uint4 aH[8], aL[8];
                #pragma unroll
                for (int k = 0; k < 8; ++k) {
                    aH[k] = __ldcg((const uint4*)&s1[k * 128 + lane * 4]);
                    aL[k] = __ldcg((const uint4*)&s1[1024 + k * 128 + lane * 4]);
                }
                #pragma unroll
                for (int k = 0; k < 8; ++k) {
                    int p = k & 1;
                    uint2 bH = *(uint2*)&sw[((0 * 16 + 8 + k) * 8 + wi) * 64 + lane * 2];
                    uint2 bL = *(uint2*)&sw[((1 * 16 + 8 + k) * 8 + wi) * 64 + lane * 2];
                    IMMA16832(accA[p], aH[k], bH);
                    IMMA16832(accB[p], aH[k], bL);
                    IMMA16832(accC[p], aL[k], bH);
                }
            }

            // phase 2: h0(t) from layer0
            if (tid == 0) { while ((int)ld_acq_u(&g_cnt0[g32]) < 2 * (t + 1)) { } }
            __syncthreads();
            {
                const uint* s0 = g_h0F[t & 3][g];
                uint4 aH[8], aL[8];
                #pragma unroll
                for (int k = 0; k < 8; ++k) {
                    aH[k] = __ldcg((const uint4*)&s0[k * 128 + lane * 4]);
                    aL[k] = __ldcg((const uint4*)&s0[1024 + k * 128 + lane * 4]);
                }
                #pragma unroll
                for (int k = 0; k < 8; ++k) {
                    int p = k & 1;
                    uint2 bH = *(uint2*)&sw[((0 * 16 + k) * 8 + wi) * 64 + lane * 2];
                    uint2 bL = *(uint2*)&sw[((1 * 16 + k) * 8 + wi) * 64 + lane * 2];
                    IMMA16832(accA[p], aH[k], bH);
                    IMMA16832(accB[p], aH[k], bL);
                    IMMA16832(accC[p], aL[k], bH);
                }
            }

            // epilogue
            float d[4];
            #pragma unroll
            for (int q = 0; q < 4; ++q) {
                int iA = accA[0][q] + accA[1][q];
                int iBC = accB[0][q] + accB[1][q] + accC[0][q] + accC[1][q];
                d[q] = (float)iA * S16C + (float)iBC * S8C;
            }
            float v00 = tanh_fast(d[0] + bbx);
            float v01 = tanh_fast(d[1] + bby);
            float v10 = tanh_fast(d[2] + bbx);
            float v11 = tanh_fast(d[3] + bby);
            {
                int h00,l00,h01_,l01_,h10,l10,h11,l11;
                qlimbs(v00, 16384.f, h00, l00); qlimbs(v01, 16384.f, h01_, l01_);
                qlimbs(v10, 16384.f, h10, l10); qlimbs(v11, 16384.f, h11, l11);
                uint* ring = g_h1F[t & 3][g];
                int cc = jb;
                int ksb_c = cc >> 5;
                int lane_c = (gID << 2) | ((cc & 15) >> 2);
                int idx0 = ksb_c * 128 + lane_c * 4 + (((cc >> 4) & 1) << 1);
                int boff = cc & 2;
                *(unsigned short*)((char*)(ring + idx0) + boff)            = pack2s(h00, h01_);
                *(unsigned short*)((char*)(ring + idx0 + 1) + boff)        = pack2s(h10, h11);
                *(unsigned short*)((char*)(ring + 1024 + idx0) + boff)     = pack2s(l00, l01_);
                *(unsigned short*)((char*)(ring + 1024 + idx0 + 1) + boff) = pack2s(l10, l11);
            }

            __syncthreads();
            if (tid == 0) arrive_acqrel(&g_cnt1[g32]);

            // non-consumed fp32 stores after release edge
            __stcs((float2*)&g_h1all[((size_t)t * BB + b0 + gID) * HH + jb], make_float2(v00, v01));
            __stcs((float2*)&g_h1all[((size_t)t * BB + b0 + gID + 8) * HH + jb], make_float2(v10, v11));
            if (t == TT - 1) {
                *(float2*)&g_h1last[(b0 + gID) * HH + jb]     = make_float2(v00, v01);
                *(float2*)&g_h1last[(b0 + gID + 8) * HH + jb] = make_float2(v10, v11);
            }
        }
    }
}

// =====================================================================
// Epilogue: logits = h1all @ fc_w^T + fc_b; copy last hidden.
// =====================================================================
__global__ void __launch_bounds__(256) k_epilogue(
    const float* __restrict__ fcw, const float* __restrict__ fcb,
    float* __restrict__ out, int out_size)
{
    int bx = blockIdx.x, tid = threadIdx.x;
    if (bx >= 32768) {
        int i = (bx - 32768) * 256 + tid;
        int base = TT * BB * 2;
        if (base + i < out_size) {
            float v = (i < BB * HH) ? g_h0last[i] : g_h1last[i - BB * HH];
            out[base + i] = v;
        }
        return;
    }
    __shared__ float sfw[2 * HH];
    __shared__ float sfb[2];
    for (int i = tid; i < 2 * HH; i += 256) sfw[i] = fcw[i];
    if (tid < 2) sfb[tid] = fcb[tid];
    __syncthreads();

    int w = tid >> 5, lane = tid & 31;
    size_t row = (size_t)bx * 8 + w;
    const float* hp = &g_h1all[row * HH + lane * 8];
    float4 h0v = *(const float4*)hp;
    float4 h1v = *(const float4*)(hp + 4);
    const float* w0 = &sfw[lane * 8];
    const float* w1 = &sfw[HH + lane * 8];
    float c0 = 0.f, c1 = 0.f;
    #pragma unroll
    for (int q = 0; q < 4; ++q) {
        c0 += (&h0v.x)[q] * w0[q] + (&h1v.x)[q] * w0[q + 4];
        c1 += (&h0v.x)[q] * w1[q] + (&h1v.x)[q] * w1[q + 4];
    }
    #pragma unroll
    for (int off = 16; off > 0; off >>= 1) {
        c0 += __shfl_down_sync(0xFFFFFFFFu, c0, off);
        c1 += __shfl_down_sync(0xFFFFFFFFu, c1, off);
    }
    if (lane == 0) {
        out[row * 2 + 0] = c0 + sfb[0];
        out[row * 2 + 1] = c1 + sfb[1];
    }
}

// ---------------- launch ----------------
extern "C" void kernel_launch(void* const* d_in, const int* in_sizes, int n_in,
                              void* d_out, int out_size) {
    const float* inp    = (const float*)d_in[0];
    const float* hidden = (const float*)d_in[1];
    const float* Wih0   = (const float*)d_in[2];
    const float* bih0   = (const float*)d_in[3];
    const float* Whh0   = (const float*)d_in[4];
    const float* bhh0   = (const float*)d_in[5];
    const float* bias0  = (const float*)d_in[6];
    const float* Wih1   = (const float*)d_in[7];
    const float* bih1   = (const float*)d_in[8];
    const float* Whh1   = (const float*)d_in[9];
    const float* bhh1   = (const float*)d_in[10];
    const float* bias1  = (const float*)d_in[11];
    const float* fcw    = (const float*)d_in[12];
    const float* fcb    = (const float*)d_in[13];
    float* out = (float*)d_out;

    static bool attr_done = false;
    if (!attr_done) {
        cudaFuncSetAttribute(k_pro2, cudaFuncAttributeMaxDynamicSharedMemorySize, PRO2_SMEM);
        cudaFuncSetAttribute(k_rnn,  cudaFuncAttributeMaxDynamicSharedMemorySize, RNN_SMEM);
        attr_done = true;
    }

    k_seed<<<9, 256>>>(hidden);
    k_pro2<<<148, 256, PRO2_SMEM>>>(inp, Wih0, bih0, bhh0, bias0);
    k_rnn<<<96, 256, RNN_SMEM>>>(Whh0, Wih1, Whh1, bih1, bhh1, bias1);
    k_epilogue<<<33280, 256>>>(fcw, fcb, out, out_size);
}

// round 17
// speedup vs baseline: 1.0933x; 1.0933x over previous
#include <cuda_runtime.h>
#include <cuda_bf16.h>
#include <cstddef>

#define TT    1024
#define BB    256
#define INDIM 128
#define HH    256
#define NG    16     // batch groups of 16 rows; 8 CTAs each (4 layer0 + 4 layer1)

typedef unsigned long long ull;
typedef unsigned int uint;

// ---------------- scratch (device globals) ----------------
__device__ float g_X0[(size_t)TT * BB * HH];      // input proj + biases (fp32)
__device__ float g_h1all[(size_t)TT * BB * HH];   // all layer-1 hidden (fp32, for logits)
__device__ float g_h0last[BB * HH];
__device__ float g_h1last[BB * HH];
// s8 A-fragment rings (IMMA m16n8k32 layout), group-local:
// uint idx = ver*1024 + ksb*128 + lane*4 + reg ; byte of uint = k&3
__device__ uint g_h0F[4][NG][2048];
__device__ uint g_h1F[4][NG][2048];
__device__ __align__(128) unsigned g_cnt0[NG * 32];   // 4 arrivals per step
__device__ __align__(128) unsigned g_cnt1[NG * 32];   // 4 arrivals per step

// ---------------- acq/rel primitives ----------------
__device__ __forceinline__ unsigned arrive_acqrel(unsigned* p) {
    unsigned r;
    asm volatile("atom.acq_rel.gpu.global.add.u32 %0, [%1], 1;" : "=r"(r) : "l"(p) : "memory");
    return r;
}
__device__ __forceinline__ unsigned ld_acq_u(const unsigned* p) {
    unsigned r;
    asm volatile("ld.acquire.gpu.global.u32 %0, [%1];" : "=r"(r) : "l"(p) : "memory");
    return r;
}

__device__ __forceinline__ float tanh_fast(float x) {
    float xc = fminf(fmaxf(x, -15.0f), 15.0f);
    float e  = __expf(2.0f * xc);
    return __fdividef(e - 1.0f, e + 1.0f);
}
// bf16 split (prologue only)
__device__ __forceinline__ void split2(float a, float b, uint& hi, uint& lo) {
    __nv_bfloat162 h = __floats2bfloat162_rn(a, b);
    float ha = __bfloat162float(h.x), hb = __bfloat162float(h.y);
    __nv_bfloat162 l = __floats2bfloat162_rn(a - ha, b - hb);
    hi = *(uint*)&h; lo = *(uint*)&l;
}
// s16 fixed-point limb split
__device__ __forceinline__ void qlimbs(float v, float scale, int& hi, int& lo) {
    int q = __float2int_rn(v * scale);
    hi = (q + 128) >> 8;
    lo = q - (hi << 8);
}
__device__ __forceinline__ uint pack4(int a, int b, int c, int d) {
    return (uint)(unsigned char)a | ((uint)(unsigned char)b << 8) |
           ((uint)(unsigned char)c << 16) | ((uint)(unsigned char)d << 24);
}
__device__ __forceinline__ unsigned short pack2s(int a, int b) {
    return (unsigned short)((uint)(unsigned char)a | ((uint)(unsigned char)b << 8));
}

#define MMA16816(d, a, b) \
    asm volatile("mma.sync.aligned.m16n8k16.row.col.f32.bf16.bf16.f32 " \
        "{%0,%1,%2,%3}, {%4,%5,%6,%7}, {%8,%9}, {%0,%1,%2,%3};" \
        : "+f"(d[0]), "+f"(d[1]), "+f"(d[2]), "+f"(d[3]) \
        : "r"((a).x), "r"((a).y), "r"((a).z), "r"((a).w), "r"((b).x), "r"((b).y))

#define IMMA16832(d, a, b) \
    asm volatile("mma.sync.aligned.m16n8k32.row.col.s32.s8.s8.s32 " \
        "{%0,%1,%2,%3}, {%4,%5,%6,%7}, {%8,%9}, {%0,%1,%2,%3};" \
        : "+r"((d)[0]), "+r"((d)[1]), "+r"((d)[2]), "+r"((d)[3]) \
        : "r"((a).x), "r"((a).y), "r"((a).z), "r"((a).w), "r"((b).x), "r"((b).y))

#define S16C 3.0517578125e-05f        // 2^-15
#define S8C  1.1920928955078125e-07f  // 2^-23

// =====================================================================
// Seed: pack initial hidden into s8 limb frag rings (slot 3); reset counters.
// =====================================================================
__global__ void __launch_bounds__(256) k_seed(const float* __restrict__ hidden) {
    int bx = blockIdx.x, tid = threadIdx.x;
    if (bx == 8) {
        if (tid < NG) { g_cnt0[tid * 32] = 0; g_cnt1[tid * 32] = 0; }
        return;
    }
    for (int s = 0; s < 16; ++s) {
        int it = bx * 4096 + s * 256 + tid;        // 0..32767
        int tensor = it >> 14;
        int rem = it & 16383;
        int b = rem >> 6, k4 = (rem & 63) << 2;
        float4 hv = *(const float4*)&hidden[(size_t)tensor * BB * HH + b * HH + k4];
        int h0,l0,h1,l1,h2,l2,h3,l3;
        qlimbs(hv.x, 16384.f, h0, l0); qlimbs(hv.y, 16384.f, h1, l1);
        qlimbs(hv.z, 16384.f, h2, l2); qlimbs(hv.w, 16384.f, h3, l3);
        uint uH = pack4(h0,h1,h2,h3), uL = pack4(l0,l1,l2,l3);
        int r = b & 15, grp = b >> 4;
        int lane = ((r & 7) << 2) | ((k4 >> 2) & 3);
        int reg = ((r >> 3) & 1) | (((k4 >> 4) & 1) << 1);
        int idx = (k4 >> 5) * 128 + lane * 4 + reg;
        uint* ring = (tensor == 0) ? g_h0F[3][grp] : g_h1F[3][grp];
        ring[idx] = uH; ring[1024 + idx] = uL;
    }
}

// =====================================================================
// Prologue (tensor-core bf16 3-term, validated R13): X0 = inp @ Wih0^T + biases.
// =====================================================================
#define PRO2_SMEM 157184
__global__ void __launch_bounds__(256, 1) k_pro2(
    const float* __restrict__ inp, const float* __restrict__ Wih0,
    const float* __restrict__ bih0, const float* __restrict__ bhh0,
    const float* __restrict__ bias0)
{
    extern __shared__ char smch[];
    uint*  sw   = (uint*)smch;
    float* sa   = (float*)(smch + 131072);
    float* sout = (float*)(smch + 139520);
    float* sb   = (float*)(smch + 156160);

    const int bx = blockIdx.x, tid = threadIdx.x;
    const int lane = tid & 31, wi = tid >> 5;
    const int gID = lane >> 2, tig = lane & 3;
    const int acol = tig * 2;

    for (int i = tid; i < 8192; i += 256) {
        int j = i >> 5, k4 = (i & 31) << 2;
        float4 w = *(const float4*)&Wih0[(size_t)j * INDIM + k4];
        uint h01, l01, h23, l23;
        split2(w.x, w.y, h01, l01);
        split2(w.z, w.w, h23, l23);
        int lane0 = ((j & 7) << 2) | ((k4 >> 1) & 3);
        int reg = (k4 >> 3) & 1, ksb = k4 >> 4, ng = j >> 3;
        int b0 = ((0 * 8 + ksb) * 32 + ng) * 32;
        int b1 = ((1 * 8 + ksb) * 32 + ng) * 32;
        sw[(b0 + lane0) * 2 + reg]     = h01;
        sw[(b0 + lane0 + 1) * 2 + reg] = h23;
        sw[(b1 + lane0) * 2 + reg]     = l01;
        sw[(b1 + lane0 + 1) * 2 + reg] = l23;
    }
    if (tid < 256) sb[tid] = bih0[tid] + bhh0[tid] + bias0[tid];
    __syncthreads();

    for (int mt = bx; mt < 16384; mt += 148) {
        const size_t r0 = (size_t)mt * 16;
        #pragma unroll
        for (int it = 0; it < 2; ++it) {
            int i = tid + it * 256;
            int row = i >> 5, c4 = (i & 31) << 2;
            *(float4*)&sa[row * 132 + c4] = *(const float4*)&inp[(r0 + row) * INDIM + c4];
        }
        __syncthreads();

        uint4 aH[8], aL[8];
        #pragma unroll
        for (int ksb = 0; ksb < 8; ++ksb) {
            int cb = ksb * 16 + acol;
            float2 p0 = *(const float2*)&sa[gID * 132 + cb];
            float2 p1 = *(const float2*)&sa[(gID + 8) * 132 + cb];
            float2 p2 = *(const float2*)&sa[gID * 132 + cb + 8];
            float2 p3 = *(const float2*)&sa[(gID + 8) * 132 + cb + 8];
            split2(p0.x, p0.y, aH[ksb].x, aL[ksb].x);
            split2(p1.x, p1.y, aH[ksb].y, aL[ksb].y);
            split2(p2.x, p2.y, aH[ksb].z, aL[ksb].z);
            split2(p3.x, p3.y, aH[ksb].w, aL[ksb].w);
        }

        float acc[4][4];
        #pragma unroll
        for (int n2 = 0; n2 < 4; ++n2)
            #pragma unroll
            for (int q = 0; q < 4; ++q) acc[n2][q] = 0.0f;

        #pragma unroll
        for (int ksb = 0; ksb < 8; ++ksb) {
            #pragma unroll
            for (int n2 = 0; n2 < 4; ++n2) {
                int ngg = wi * 4 + n2;
                uint2 bH = *(const uint2*)&sw[(((0 * 8 + ksb) * 32 + ngg) * 32 + lane) * 2];
                uint2 bL = *(const uint2*)&sw[(((1 * 8 + ksb) * 32 + ngg) * 32 + lane) * 2];
                MMA16816(acc[n2], aH[ksb], bH);
                MMA16816(acc[n2], aL[ksb], bH);
                MMA16816(acc[n2], aH[ksb], bL);
            }
        }
        __syncthreads();

        #pragma unroll
        for (int n2 = 0; n2 < 4; ++n2) {
            int j = (wi * 4 + n2) * 8 + acol;
            float2 bb = *(const float2*)&sb[j];
            *(float2*)&sout[gID * 260 + j]       = make_float2(acc[n2][0] + bb.x, acc[n2][1] + bb.y);
            *(float2*)&sout[(gID + 8) * 260 + j] = make_float2(acc[n2][2] + bb.x, acc[n2][3] + bb.y);
        }
        __syncthreads();

        #pragma unroll
        for (int it = 0; it < 4; ++it) {
            int li = tid + it * 256;
            int row = li >> 6, c4 = (li & 63) << 2;
            *(float4*)&g_X0[(r0 + row) * HH + c4] = *(const float4*)&sout[row * 260 + c4];
        }
        __syncthreads();
    }
}

// =====================================================================
// Persistent recurrence, INT8 IMMA v4: 16 groups x 8 CTAs (128 total).
// roles 0-3: layer0 n=64 slices (24 IMMA/warp).
// roles 4-7: layer1 n=64 slices, two-phase (h1 part early, h0 part late).
// =====================================================================
#define RNN_SMEM 65536
__global__ void __launch_bounds__(256, 1) k_rnn(
    const float* __restrict__ Whh0, const float* __restrict__ Wih1,
    const float* __restrict__ Whh1, const float* __restrict__ bih1,
    const float* __restrict__ bhh1, const float* __restrict__ bias1)
{
    extern __shared__ uint smu[];
    const int bx = blockIdx.x, tid = threadIdx.x;
    const int lane = tid & 31, wi = tid >> 5;
    const int gID = lane >> 2, tig = lane & 3;
    const int g = bx >> 3, role = bx & 7, g32 = g * 32;
    const int b0 = g * 16;
    uint* sw = smu;

    if (role < 4) {
        // ================= layer 0: m16 x n64 x k256 =================
        const int jg0 = role * 64;

        // W frag staging: 64 rows x 256 cols = 4096 float4s
        // sw layout: [2 ver][8 ksb][8 ng][32 lane][2 reg] = 8192 uints
        for (int i = tid; i < 4096; i += 256) {
            int jl = i >> 6, k4 = (i & 63) << 2;
            float4 w = *(const float4*)&Whh0[(size_t)(jg0 + jl) * HH + k4];
            int h0,l0,h1,l1,h2,l2,h3,l3;
            qlimbs(w.x, 131072.f, h0, l0); qlimbs(w.y, 131072.f, h1, l1);
            qlimbs(w.z, 131072.f, h2, l2); qlimbs(w.w, 131072.f, h3, l3);
            int lane0 = ((jl & 7) << 2) | ((k4 >> 2) & 3);
            int reg = (k4 >> 4) & 1, ksb = k4 >> 5, ng = jl >> 3;
            sw[(((0 * 8 + ksb) * 8 + ng) * 64) + lane0 * 2 + reg] = pack4(h0,h1,h2,h3);
            sw[(((1 * 8 + ksb) * 8 + ng) * 64) + lane0 * 2 + reg] = pack4(l0,l1,l2,l3);
        }

        const int cc = jg0 + wi * 8 + 2 * tig;   // this thread's 2 output cols

        for (int t = 0; t < TT; ++t) {
            if (tid == 0)       { while ((int)ld_acq_u(&g_cnt0[g32]) < 4 * t) { } }
            else if (tid == 32) { while ((int)ld_acq_u(&g_cnt1[g32]) < 4 * (t - 3)) { } }
            __syncthreads();

            // direct-LDG A = h0(t-1) frags (lane-identical layout)
            const uint* srcA = g_h0F[(t + 3) & 3][g];
            uint4 aH[8], aL[8];
            #pragma unroll
            for (int ksb = 0; ksb < 8; ++ksb) {
                aH[ksb] = __ldcg((const uint4*)&srcA[ksb * 128 + lane * 4]);
                aL[ksb] = __ldcg((const uint4*)&srcA[1024 + ksb * 128 + lane * 4]);
            }

            // X0 prefetch
            float2 px0 = __ldcs((const float2*)&g_X0[((size_t)t * BB + b0 + gID) * HH + cc]);
            float2 px1 = __ldcs((const float2*)&g_X0[((size_t)t * BB + b0 + gID + 8) * HH + cc]);

            int accA[4], accB[4], accC[4];
            #pragma unroll
            for (int q = 0; q < 4; ++q) { accA[q] = 0; accB[q] = 0; accC[q] = 0; }

            #pragma unroll
            for (int ksb = 0; ksb < 8; ++ksb) {
                uint2 bH = *(uint2*)&sw[((0 * 8 + ksb) * 8 + wi) * 64 + lane * 2];
                uint2 bL = *(uint2*)&sw[((1 * 8 + ksb) * 8 + wi) * 64 + lane * 2];
                IMMA16832(accA, aH[ksb], bH);
                IMMA16832(accB, aH[ksb], bL);
                IMMA16832(accC, aL[ksb], bH);
            }

            // epilogue
            float d0 = (float)accA[0] * S16C + (float)(accB[0] + accC[0]) * S8C;
            float d1 = (float)accA[1] * S16C + (float)(accB[1] + accC[1]) * S8C;
            float d2 = (float)accA[2] * S16C + (float)(accB[2] + accC[2]) * S8C;
            float d3 = (float)accA[3] * S16C + (float)(accB[3] + accC[3]) * S8C;
            float v00 = tanh_fast(d0 + px0.x);
            float v01 = tanh_fast(d1 + px0.y);
            float v10 = tanh_fast(d2 + px1.x);
            float v11 = tanh_fast(d3 + px1.y);
            {
                int h00,l00,h01_,l01_,h10,l10,h11,l11;
                qlimbs(v00, 16384.f, h00, l00); qlimbs(v01, 16384.f, h01_, l01_);
                qlimbs(v10, 16384.f, h10, l10); qlimbs(v11, 16384.f, h11, l11);
                uint* ring = g_h0F[t & 3][g];
                int ksb_c = cc >> 5;
                int lane_c = (gID << 2) | ((cc & 15) >> 2);
                int idx0 = ksb_c * 128 + lane_c * 4 + (((cc >> 4) & 1) << 1);
                int boff = cc & 2;
                *(unsigned short*)((char*)(ring + idx0) + boff)            = pack2s(h00, h01_);
                *(unsigned short*)((char*)(ring + idx0 + 1) + boff)        = pack2s(h10, h11);
                *(unsigned short*)((char*)(ring + 1024 + idx0) + boff)     = pack2s(l00, l01_);
                *(unsigned short*)((char*)(ring + 1024 + idx0 + 1) + boff) = pack2s(l10, l11);
            }

            __syncthreads();
            if (tid == 0) arrive_acqrel(&g_cnt0[g32]);

            if (t == TT - 1) {
                *(float2*)&g_h0last[(b0 + gID) * HH + cc]     = make_float2(v00, v01);
                *(float2*)&g_h0last[(b0 + gID + 8) * HH + cc] = make_float2(v10, v11);
            }
        }
    } else {
        // ================= layer 1: m16 x n64 x k512, two-phase =================
        const int q64 = role - 4;
        const int jq0 = q64 * 64;

        // sw layout: [2 ver][16 ksb][8 ng][32 lane][2 reg] = 16384 uints
        for (int i = tid; i < 8192; i += 256) {
            int jl = i >> 7, k4 = (i & 127) << 2;
            float4 w = (k4 < 256)
                ? *(const float4*)&Wih1[(size_t)(jq0 + jl) * HH + k4]
                : *(const float4*)&Whh1[(size_t)(jq0 + jl) * HH + (k4 - 256)];
            int h0,l0,h1,l1,h2,l2,h3,l3;
            qlimbs(w.x, 131072.f, h0, l0); qlimbs(w.y, 131072.f, h1, l1);
            qlimbs(w.z, 131072.f, h2, l2); qlimbs(w.w, 131072.f, h3, l3);
            int lane0 = ((jl & 7) << 2) | ((k4 >> 2) & 3);
            int reg = (k4 >> 4) & 1, ksb = k4 >> 5, ng = jl >> 3;
            sw[(((0 * 16 + ksb) * 8 + ng) * 64) + lane0 * 2 + reg] = pack4(h0,h1,h2,h3);
            sw[(((1 * 16 + ksb) * 8 + ng) * 64) + lane0 * 2 + reg] = pack4(l0,l1,l2,l3);
        }

        const int jb = jq0 + wi * 8 + 2 * tig;
        const float bbx = bih1[jb] + bhh1[jb] + bias1[jb];
        const float bby = bih1[jb + 1] + bhh1[jb + 1] + bias1[jb + 1];

        for (int t = 0; t < TT; ++t) {
            int accA[2][4], accB[2][4], accC[2][4];
            #pragma unroll
            for (int p = 0; p < 2; ++p)
                #pragma unroll
                for (int q = 0; q < 4; ++q) { accA[p][q] = 0; accB[p][q] = 0; accC[p][q] = 0; }

            // phase 1: peers' h1(t-1) — only intra-layer1 skew
            if (tid == 0) { while ((int)ld_acq_u(&g_cnt1[g32]) < 4 * t) { } }
            __syncthreads();
            {
                const uint* s1 = g_h1F[(t + 3) & 3][g];
                uint4 aH[8], aL[8];
                #pragma unroll
                for (int k = 0; k < 8; ++k) {
                    aH[k] = __ldcg((const uint4*)&s1[k * 128 + lane * 4]);
                    aL[k] = __ldcg((const uint4*)&s1[1024 + k * 128 + lane * 4]);
                }
                #pragma unroll
                for (int k = 0; k < 8; ++k) {
                    int p = k & 1;
                    uint2 bH = *(uint2*)&sw[((0 * 16 + 8 + k) * 8 + wi) * 64 + lane * 2];
                    uint2 bL = *(uint2*)&sw[((1 * 16 + 8 + k) * 8 + wi) * 64 + lane * 2];
                    IMMA16832(accA[p], aH[k], bH);
                    IMMA16832(accB[p], aH[k], bL);
                    IMMA16832(accC[p], aL[k], bH);
                }
            }

            // phase 2: h0(t) from layer0 (real dependency, 4 arrivals)
            if (tid == 0) { while ((int)ld_acq_u(&g_cnt0[g32]) < 4 * (t + 1)) { } }
            __syncthreads();
            {
                const uint* s0 = g_h0F[t & 3][g];
                uint4 aH[8], aL[8];
                #pragma unroll
                for (int k = 0; k < 8; ++k) {
                    aH[k] = __ldcg((const uint4*)&s0[k * 128 + lane * 4]);
                    aL[k] = __ldcg((const uint4*)&s0[1024 + k * 128 + lane * 4]);
                }
                #pragma unroll
                for (int k = 0; k < 8; ++k) {
                    int p = k & 1;
                    uint2 bH = *(uint2*)&sw[((0 * 16 + k) * 8 + wi) * 64 + lane * 2];
                    uint2 bL = *(uint2*)&sw[((1 * 16 + k) * 8 + wi) * 64 + lane * 2];
                    IMMA16832(accA[p], aH[k], bH);
                    IMMA16832(accB[p], aH[k], bL);
                    IMMA16832(accC[p], aL[k], bH);
                }
            }

            // epilogue
            float d[4];
            #pragma unroll
            for (int q = 0; q < 4; ++q) {
                int iA = accA[0][q] + accA[1][q];
                int iBC = accB[0][q] + accB[1][q] + accC[0][q] + accC[1][q];
                d[q] = (float)iA * S16C + (float)iBC * S8C;
            }
            float v00 = tanh_fast(d[0] + bbx);
            float v01 = tanh_fast(d[1] + bby);
            float v10 = tanh_fast(d[2] + bbx);
            float v11 = tanh_fast(d[3] + bby);
            {
                int h00,l00,h01_,l01_,h10,l10,h11,l11;
                qlimbs(v00, 16384.f, h00, l00); qlimbs(v01, 16384.f, h01_, l01_);
                qlimbs(v10, 16384.f, h10, l10); qlimbs(v11, 16384.f, h11, l11);
                uint* ring = g_h1F[t & 3][g];
                int cc = jb;
                int ksb_c = cc >> 5;
                int lane_c = (gID << 2) | ((cc & 15) >> 2);
                int idx0 = ksb_c * 128 + lane_c * 4 + (((cc >> 4) & 1) << 1);
                int boff = cc & 2;
                *(unsigned short*)((char*)(ring + idx0) + boff)            = pack2s(h00, h01_);
                *(unsigned short*)((char*)(ring + idx0 + 1) + boff)        = pack2s(h10, h11);
                *(unsigned short*)((char*)(ring + 1024 + idx0) + boff)     = pack2s(l00, l01_);
                *(unsigned short*)((char*)(ring + 1024 + idx0 + 1) + boff) = pack2s(l10, l11);
            }

            __syncthreads();
            if (tid == 0) arrive_acqrel(&g_cnt1[g32]);

            // non-consumed fp32 stores after release edge
            __stcs((float2*)&g_h1all[((size_t)t * BB + b0 + gID) * HH + jb], make_float2(v00, v01));
            __stcs((float2*)&g_h1all[((size_t)t * BB + b0 + gID + 8) * HH + jb], make_float2(v10, v11));
            if (t == TT - 1) {
                *(float2*)&g_h1last[(b0 + gID) * HH + jb]     = make_float2(v00, v01);
                *(float2*)&g_h1last[(b0 + gID + 8) * HH + jb] = make_float2(v10, v11);
            }
        }
    }
}

// =====================================================================
// Epilogue: logits = h1all @ fc_w^T + fc_b; copy last hidden.
// =====================================================================
__global__ void __launch_bounds__(256) k_epilogue(
    const float* __restrict__ fcw, const float* __restrict__ fcb,
    float* __restrict__ out, int out_size)
{
    int bx = blockIdx.x, tid = threadIdx.x;
    if (bx >= 32768) {
        int i = (bx - 32768) * 256 + tid;
        int base = TT * BB * 2;
        if (base + i < out_size) {
            float v = (i < BB * HH) ? g_h0last[i] : g_h1last[i - BB * HH];
            out[base + i] = v;
        }
        return;
    }
    __shared__ float sfw[2 * HH];
    __shared__ float sfb[2];
    for (int i = tid; i < 2 * HH; i += 256) sfw[i] = fcw[i];
    if (tid < 2) sfb[tid] = fcb[tid];
    __syncthreads();

    int w = tid >> 5, lane = tid & 31;
    size_t row = (size_t)bx * 8 + w;
    const float* hp = &g_h1all[row * HH + lane * 8];
    float4 h0v = *(const float4*)hp;
    float4 h1v = *(const float4*)(hp + 4);
    const float* w0 = &sfw[lane * 8];
    const float* w1 = &sfw[HH + lane * 8];
    float c0 = 0.f, c1 = 0.f;
    #pragma unroll
    for (int q = 0; q < 4; ++q) {
        c0 += (&h0v.x)[q] * w0[q] + (&h1v.x)[q] * w0[q + 4];
        c1 += (&h0v.x)[q] * w1[q] + (&h1v.x)[q] * w1[q + 4];
    }
    #pragma unroll
    for (int off = 16; off > 0; off >>= 1) {
        c0 += __shfl_down_sync(0xFFFFFFFFu, c0, off);
        c1 += __shfl_down_sync(0xFFFFFFFFu, c1, off);
    }
    if (lane == 0) {
        out[row * 2 + 0] = c0 + sfb[0];
        out[row * 2 + 1] = c1 + sfb[1];
    }
}

// ---------------- launch ----------------
extern "C" void kernel_launch(void* const* d_in, const int* in_sizes, int n_in,
                              void* d_out, int out_size) {
    const float* inp    = (const float*)d_in[0];
    const float* hidden = (const float*)d_in[1];
    const float* Wih0   = (const float*)d_in[2];
    const float* bih0   = (const float*)d_in[3];
    const float* Whh0   = (const float*)d_in[4];
    const float* bhh0   = (const float*)d_in[5];
    const float* bias0  = (const float*)d_in[6];
    const float* Wih1   = (const float*)d_in[7];
    const float* bih1   = (const float*)d_in[8];
    const float* Whh1   = (const float*)d_in[9];
    const float* bhh1   = (const float*)d_in[10];
    const float* bias1  = (const float*)d_in[11];
    const float* fcw    = (const float*)d_in[12];
    const float* fcb    = (const float*)d_in[13];
    float* out = (float*)d_out;

    static bool attr_done = false;
    if (!attr_done) {
        cudaFuncSetAttribute(k_pro2, cudaFuncAttributeMaxDynamicSharedMemorySize, PRO2_SMEM);
        cudaFuncSetAttribute(k_rnn,  cudaFuncAttributeMaxDynamicSharedMemorySize, RNN_SMEM);
        attr_done = true;
    }

    k_seed<<<9, 256>>>(hidden);
    k_pro2<<<148, 256, PRO2_SMEM>>>(inp, Wih0, bih0, bhh0, bias0);
    k_rnn<<<128, 256, RNN_SMEM>>>(Whh0, Wih1, Whh1, bih1, bhh1, bias1);
    k_epilogue<<<33280, 256>>>(fcw, fcb, out, out_size);
}